// round 11
// baseline (speedup 1.0000x reference)
#include <cuda_runtime.h>
#include <stdint.h>
#include <math.h>

#define Bb 4
#define Ss 128
#define Nn 512
#define Hh 64
#define Mm 2048
#define XS 68        // fp32 tile stride (scalar LDS banks 4g+q: conflict-free)
#define WS 72        // split-tile stride (paired LDS.64 banks 8g+2q: conflict-free)
#define SSTR 132
#define NTH 1024

// smem float offsets
#define F_R1   0       // Xtr fp32 [128][68] -> P fp32 -> scores[0:8704)
#define F_XH   8704    // XtxH [128][72] k-pair-permuted -> scores[8704:17920)
#define F_XL   17920   // XtxL [128][72]  (dead after phase 3)
#define F_W    27136   // G[64][68] | Wv[64][68] -> V fp32 [128][68]
#define F_TAIL 35840   // rb128 cb128 sg64 sb64 sbv64
#define SMEM_FLOATS 36288   // 145152 B -> 1 CTA/SM

// ---------------- precomputed operands ----------------
__device__ float g_Gt[Hh*Hh];   // [c][h] = scale * sum_o Wq[o][h] Wk[o][c]
__device__ float g_u[Hh];
__device__ float g_w[Hh];
__device__ float g_c0;

__global__ void precompute_k(const float* __restrict__ Wq, const float* __restrict__ bq,
                             const float* __restrict__ Wk, const float* __restrict__ bk) {
    int gid = blockIdx.x * blockDim.x + threadIdx.x;
    const float scale = 0.125f;
    if (gid < Hh * Hh) {
        int c = gid >> 6, h = gid & 63;
        float s = 0.f;
        #pragma unroll 8
        for (int o = 0; o < Hh; o++) s += Wq[o*Hh + h] * Wk[o*Hh + c];
        g_Gt[gid] = s * scale;
    }
    if (gid < Hh) {
        float s = 0.f, t = 0.f;
        #pragma unroll 8
        for (int o = 0; o < Hh; o++) { s += Wq[o*Hh + gid] * bk[o]; t += Wk[o*Hh + gid] * bq[o]; }
        g_u[gid] = s * scale;
        g_w[gid] = t * scale;
    }
    if (gid == 0) {
        float s = 0.f;
        for (int o = 0; o < Hh; o++) s += bq[o] * bk[o];
        g_c0 = s * scale;
    }
}

// ---------------- device helpers ----------------
__device__ __forceinline__ void tf32x2(float x, uint32_t& h, uint32_t& l) {
    asm("cvt.rna.tf32.f32 %0, %1;" : "=r"(h) : "f"(x));
    float r = x - __uint_as_float(h);
    asm("cvt.rna.tf32.f32 %0, %1;" : "=r"(l) : "f"(r));
}
__device__ __forceinline__ void mma8(float c[4], uint32_t a0, uint32_t a1, uint32_t a2, uint32_t a3,
                                     uint32_t b0, uint32_t b1) {
    asm volatile(
        "mma.sync.aligned.m16n8k8.row.col.f32.tf32.tf32.f32 "
        "{%0,%1,%2,%3}, {%4,%5,%6,%7}, {%8,%9}, {%0,%1,%2,%3};"
        : "+f"(c[0]), "+f"(c[1]), "+f"(c[2]), "+f"(c[3])
        : "r"(a0), "r"(a1), "r"(a2), "r"(a3), "r"(b0), "r"(b1));
}
__device__ __forceinline__ unsigned f2mono(float v) {
    unsigned u = __float_as_uint(v);
    return (u & 0x80000000u) ? ~u : (u | 0x80000000u);
}
__device__ __forceinline__ float mono2f(unsigned k) {
    unsigned u = (k & 0x80000000u) ? (k ^ 0x80000000u) : ~k;
    return __uint_as_float(u);
}

// A fp32 on-fly, B fp32 on-fly (phase 1)
template<int NT>
__device__ __forceinline__ void gemm_ff(const float* __restrict__ A, const float* __restrict__ B,
                                        int mb, int n0, int lane, float acc[NT][4]) {
    const int g = lane >> 2, q = lane & 3;
    const float* ar0 = A + (mb + g) * XS + q;
    const float* ar1 = A + (mb + g + 8) * XS + q;
    #pragma unroll
    for (int k0 = 0; k0 < 64; k0 += 8) {
        uint32_t ah[4], al[4];
        tf32x2(ar0[k0],   ah[0], al[0]);
        tf32x2(ar1[k0],   ah[1], al[1]);
        tf32x2(ar0[k0+4], ah[2], al[2]);
        tf32x2(ar1[k0+4], ah[3], al[3]);
        #pragma unroll
        for (int nt = 0; nt < NT; nt++) {
            const float* bp = B + (n0 + 8*nt + g) * XS + k0 + q;
            uint32_t b0h, b0l, b1h, b1l;
            tf32x2(bp[0], b0h, b0l);
            tf32x2(bp[4], b1h, b1l);
            mma8(acc[nt], ah[0],ah[1],ah[2],ah[3], b0h, b1h);
            mma8(acc[nt], ah[0],ah[1],ah[2],ah[3], b0l, b1l);
            mma8(acc[nt], al[0],al[1],al[2],al[3], b0h, b1h);
        }
    }
}

// A pre-split (stride 72, k-pair-permuted), B fp32 on-fly (phase 2)
template<int NT>
__device__ __forceinline__ void gemm_pf(const float* __restrict__ AH, const float* __restrict__ AL,
                                        const float* __restrict__ B,
                                        int mb, int n0, int lane, float acc[NT][4]) {
    const int g = lane >> 2, q = lane & 3;
    const float* a0h = AH + (mb + g) * WS + 2*q;
    const float* a1h = AH + (mb + g + 8) * WS + 2*q;
    const float* a0l = AL + (mb + g) * WS + 2*q;
    const float* a1l = AL + (mb + g + 8) * WS + 2*q;
    #pragma unroll
    for (int k0 = 0; k0 < 64; k0 += 8) {
        float2 xh0 = *(const float2*)(a0h + k0);
        float2 xh1 = *(const float2*)(a1h + k0);
        float2 xl0 = *(const float2*)(a0l + k0);
        float2 xl1 = *(const float2*)(a1l + k0);
        #pragma unroll
        for (int nt = 0; nt < NT; nt++) {
            const float* bp = B + (n0 + 8*nt + g) * XS + k0 + q;
            uint32_t b0h, b0l, b1h, b1l;
            tf32x2(bp[0], b0h, b0l);
            tf32x2(bp[4], b1h, b1l);
            mma8(acc[nt], __float_as_uint(xh0.x),__float_as_uint(xh1.x),__float_as_uint(xh0.y),__float_as_uint(xh1.y), b0h, b1h);
            mma8(acc[nt], __float_as_uint(xh0.x),__float_as_uint(xh1.x),__float_as_uint(xh0.y),__float_as_uint(xh1.y), b0l, b1l);
            mma8(acc[nt], __float_as_uint(xl0.x),__float_as_uint(xl1.x),__float_as_uint(xl0.y),__float_as_uint(xl1.y), b0h, b1h);
        }
    }
}

// A fp32 on-fly, B pre-split (phase 3)
template<int NT>
__device__ __forceinline__ void gemm_fp(const float* __restrict__ A,
                                        const float* __restrict__ BH, const float* __restrict__ BL,
                                        int mb, int n0, int lane, float acc[NT][4]) {
    const int g = lane >> 2, q = lane & 3;
    const float* ar0 = A + (mb + g) * XS + q;
    const float* ar1 = A + (mb + g + 8) * XS + q;
    #pragma unroll
    for (int k0 = 0; k0 < 64; k0 += 8) {
        uint32_t ah[4], al[4];
        tf32x2(ar0[k0],   ah[0], al[0]);
        tf32x2(ar1[k0],   ah[1], al[1]);
        tf32x2(ar0[k0+4], ah[2], al[2]);
        tf32x2(ar1[k0+4], ah[3], al[3]);
        #pragma unroll
        for (int nt = 0; nt < NT; nt++) {
            int boff = (n0 + 8*nt + g) * WS + k0 + 2*q;
            float2 bh = *(const float2*)(BH + boff);
            float2 bl = *(const float2*)(BL + boff);
            mma8(acc[nt], ah[0],ah[1],ah[2],ah[3], __float_as_uint(bh.x), __float_as_uint(bh.y));
            mma8(acc[nt], ah[0],ah[1],ah[2],ah[3], __float_as_uint(bl.x), __float_as_uint(bl.y));
            mma8(acc[nt], al[0],al[1],al[2],al[3], __float_as_uint(bh.x), __float_as_uint(bh.y));
        }
    }
}

extern __shared__ float smf[];
__global__ void __launch_bounds__(NTH, 1)
fused_align_k(const float* __restrict__ traffic, const float* __restrict__ text,
              const float* __restrict__ Wv, const float* __restrict__ bv,
              const float* __restrict__ gamma, const float* __restrict__ beta,
              const int* __restrict__ topk_p,
              float* __restrict__ out_main, float* __restrict__ out_attn) {
    float* R1  = smf + F_R1;     // Xtr -> P -> scores lo
    float* XH  = smf + F_XH;     // XtxH -> scores hi
    float* XL  = smf + F_XL;     // XtxL
    float* WGV = smf + F_W;      // G|Wv -> V
    float* sc  = smf + F_R1;     // scores [128][132]
    float* rb  = smf + F_TAIL;
    float* cb  = rb + 128;
    float* sg  = cb + 128;
    float* sb  = sg + 64;
    float* sbv = sb + 64;

    const int tid = threadIdx.x;
    const int lane = tid & 31;
    const int wrp = tid >> 5;       // 0..31
    const int m = blockIdx.x;
    const int b = m >> 9;
    const int n = m & (Nn - 1);

    const float* tr_base = traffic + ((size_t)b * Ss * Nn + n) * Hh;
    const float* tx_base = text    + ((size_t)b * Ss * Nn + n) * Hh;

    // ---- Stage 0 ----
    for (int i = tid; i < 4096; i += NTH) WGV[(i >> 6) * XS + (i & 63)]        = g_Gt[i];
    for (int i = tid; i < 4096; i += NTH) WGV[4352 + (i >> 6) * XS + (i & 63)] = Wv[i];
    #pragma unroll
    for (int it = 0; it < 2; it++) {
        int i = tid + it * NTH;          // 0..2047
        int r = i >> 4, f = i & 15;
        float4 a  = *(const float4*)(tr_base + (size_t)r * Nn * Hh + f * 4);
        float4 bx = *(const float4*)(tx_base + (size_t)r * Nn * Hh + f * 4);
        *(float4*)(R1 + r * XS + f * 4) = a;
        // split Xtx -> hi/lo at k-pair-permuted positions (pairs (k,k+4) adjacent)
        uint32_t h0,l0,h1,l1,h2,l2,h3,l3;
        tf32x2(bx.x,h0,l0); tf32x2(bx.y,h1,l1); tf32x2(bx.z,h2,l2); tf32x2(bx.w,h3,l3);
        int pbase = r * WS + ((f >> 1) << 3) + (f & 1);
        XH[pbase + 0] = __uint_as_float(h0);  XL[pbase + 0] = __uint_as_float(l0);
        XH[pbase + 2] = __uint_as_float(h1);  XL[pbase + 2] = __uint_as_float(l1);
        XH[pbase + 4] = __uint_as_float(h2);  XL[pbase + 4] = __uint_as_float(l2);
        XH[pbase + 6] = __uint_as_float(h3);  XL[pbase + 6] = __uint_as_float(l3);
        // fused bias partials
        float4 uu = *(const float4*)(g_u + f * 4);
        float4 ww = *(const float4*)(g_w + f * 4);
        float pr = a.x*uu.x + a.y*uu.y + a.z*uu.z + a.w*uu.w;
        float pc = bx.x*ww.x + bx.y*ww.y + bx.z*ww.z + bx.w*ww.w;
        #pragma unroll
        for (int o = 8; o > 0; o >>= 1) {
            pr += __shfl_xor_sync(0xffffffffu, pr, o);
            pc += __shfl_xor_sync(0xffffffffu, pc, o);
        }
        if (f == 0) { rb[r] = pr + g_c0; cb[r] = pc; }
    }
    if (tid < 64) { sg[tid] = gamma[tid]; sb[tid] = beta[tid]; sbv[tid] = bv[tid]; }
    __syncthreads();

    const int g = lane >> 2, q = lane & 3;

    // ---- Phase 1: P = Xtr @ G^T (32 warps: 8 m-tiles x 4 n16-tiles) ----
    {
        float acc[2][4];
        #pragma unroll
        for (int i = 0; i < 2; i++)
            #pragma unroll
            for (int j = 0; j < 4; j++) acc[i][j] = 0.f;
        const int mb = (wrp >> 2) * 16, n0 = (wrp & 3) * 16;
        gemm_ff<2>(R1, WGV, mb, n0, lane, acc);
        __syncthreads();
        #pragma unroll
        for (int nt = 0; nt < 2; nt++) {
            int col = n0 + 8*nt + 2*q;
            *(float2*)(R1 + (mb + g) * XS + col)     = make_float2(acc[nt][0], acc[nt][1]);
            *(float2*)(R1 + (mb + g + 8) * XS + col) = make_float2(acc[nt][2], acc[nt][3]);
        }
    }
    __syncthreads();

    // ---- Phase 2: V = Xtx @ Wv^T ----
    {
        float acc[2][4];
        #pragma unroll
        for (int i = 0; i < 2; i++)
            #pragma unroll
            for (int j = 0; j < 4; j++) acc[i][j] = 0.f;
        const int mb = (wrp >> 2) * 16, n0 = (wrp & 3) * 16;
        gemm_pf<2>(XH, XL, WGV + 4352, mb, n0, lane, acc);
        __syncthreads();
        #pragma unroll
        for (int nt = 0; nt < 2; nt++) {
            int col = n0 + 8*nt + 2*q;
            *(float2*)(WGV + (mb + g) * XS + col)     = make_float2(acc[nt][0] + sbv[col], acc[nt][1] + sbv[col+1]);
            *(float2*)(WGV + (mb + g + 8) * XS + col) = make_float2(acc[nt][2] + sbv[col], acc[nt][3] + sbv[col+1]);
        }
    }
    __syncthreads();

    // ---- Phase 3: S = P @ Xtx^T (32 warps: 8 m-tiles x 4 n32-tiles) ----
    {
        float acc[4][4];
        #pragma unroll
        for (int i = 0; i < 4; i++)
            #pragma unroll
            for (int j = 0; j < 4; j++) acc[i][j] = 0.f;
        const int mb = (wrp >> 2) * 16, n0 = (wrp & 3) * 32;
        gemm_fp<4>(R1, XH, XL, mb, n0, lane, acc);
        __syncthreads();
        #pragma unroll
        for (int nt = 0; nt < 4; nt++) {
            int col = n0 + 8*nt + 2*q;
            *(float2*)(sc + (mb + g) * SSTR + col)     = make_float2(acc[nt][0], acc[nt][1]);
            *(float2*)(sc + (mb + g + 8) * SSTR + col) = make_float2(acc[nt][2], acc[nt][3]);
        }
    }
    __syncthreads();

    // ---- Stage 3: pairwise-interleaved top-k + softmax + attn + AV + LN ----
    int kk = 16;
    if (topk_p) { kk = topk_p[0]; if (kk < 1) kk = 1; if (kk > 32) kk = 32; }

    const int r0 = wrp * 4;
    float* attn_base = out_attn + (size_t)m * Ss * Ss;
    const unsigned FULL = 0xffffffffu;

    #pragma unroll
    for (int rp = 0; rp < 2; rp++) {
        const int sA = r0 + 2*rp;
        // residual prefetch (global, coalesced)
        float res0[2], res1[2];
        #pragma unroll
        for (int j = 0; j < 2; j++) {
            res0[j] = tr_base[(size_t)(sA + j) * Nn * Hh + lane];
            res1[j] = tr_base[(size_t)(sA + j) * Nn * Hh + lane + 32];
        }

        float o[2][4];
        unsigned kx[2][4], lv[2][4];
        #pragma unroll
        for (int j = 0; j < 2; j++) {
            const int s = sA + j;
            const float rbias = rb[s];
            o[j][0] = sc[s * SSTR + lane]      + rbias + cb[lane];
            o[j][1] = sc[s * SSTR + lane + 32] + rbias + cb[lane + 32];
            o[j][2] = sc[s * SSTR + lane + 64] + rbias + cb[lane + 64];
            o[j][3] = sc[s * SSTR + lane + 96] + rbias + cb[lane + 96];
            #pragma unroll
            for (int t = 0; t < 4; t++) { kx[j][t] = f2mono(o[j][t]); lv[j][t] = kx[j][t]; }
        }

        unsigned maxk[2], thrk[2], selk[2]; int seli[2];
        #pragma unroll
        for (int j = 0; j < 2; j++) { maxk[j] = 0; thrk[j] = 0; selk[j] = 0; seli[j] = 0; }

        for (int it = 0; it < kk; ++it) {
            unsigned lb[2]; int slot[2];
            #pragma unroll
            for (int j = 0; j < 2; j++) {
                lb[j] = lv[j][0]; slot[j] = 0;
                if (lv[j][1] > lb[j]) { lb[j] = lv[j][1]; slot[j] = 1; }
                if (lv[j][2] > lb[j]) { lb[j] = lv[j][2]; slot[j] = 2; }
                if (lv[j][3] > lb[j]) { lb[j] = lv[j][3]; slot[j] = 3; }
            }
            unsigned mw[2];
            #pragma unroll
            for (int j = 0; j < 2; j++) mw[j] = __reduce_max_sync(FULL, lb[j]);
            unsigned tsel[2];
            #pragma unroll
            for (int j = 0; j < 2; j++) {
                unsigned cand = (lb[j] == mw[j]) ? (unsigned)(slot[j] * 32 + lane) : 0xffffffffu;
                tsel[j] = __reduce_min_sync(FULL, cand);
            }
            #pragma unroll
            for (int j = 0; j < 2; j++) {
                if (it == 0) maxk[j] = mw[j];
                thrk[j] = mw[j];
                if (lane == (int)(tsel[j] & 31)) {
                    int js = tsel[j] >> 5;
                    if (js == 0) lv[j][0] = 0; else if (js == 1) lv[j][1] = 0;
                    else if (js == 2) lv[j][2] = 0; else lv[j][3] = 0;
                }
                if (lane == it) { selk[j] = mw[j]; seli[j] = (int)tsel[j]; }
            }
        }

        float maxv[2], z[2], inv[2];
        float e[2][4];
        #pragma unroll
        for (int j = 0; j < 2; j++) {
            maxv[j] = mono2f(maxk[j]);
            #pragma unroll
            for (int t = 0; t < 4; t++)
                e[j][t] = (kx[j][t] >= thrk[j]) ? __expf(o[j][t] - maxv[j]) : 0.f;
            z[j] = e[j][0] + e[j][1] + e[j][2] + e[j][3];
        }
        #pragma unroll
        for (int off = 16; off > 0; off >>= 1) {
            #pragma unroll
            for (int j = 0; j < 2; j++) z[j] += __shfl_xor_sync(FULL, z[j], off);
        }
        #pragma unroll
        for (int j = 0; j < 2; j++) {
            inv[j] = 1.0f / z[j];
            float* ab = attn_base + (size_t)(sA + j) * Ss;
            ab[lane]      = e[j][0] * inv[j];
            ab[lane + 32] = e[j][1] * inv[j];
            ab[lane + 64] = e[j][2] * inv[j];
            ab[lane + 96] = e[j][3] * inv[j];
        }

        float p[2];
        #pragma unroll
        for (int j = 0; j < 2; j++)
            p[j] = (lane < kk) ? __expf(mono2f(selk[j]) - maxv[j]) * inv[j] : 0.f;

        float a0[2] = {0.f, 0.f}, a1[2] = {0.f, 0.f};
        for (int i2 = 0; i2 < kk; i2++) {
            #pragma unroll
            for (int j = 0; j < 2; j++) {
                float pi = __shfl_sync(FULL, p[j], i2);
                int   ti = __shfl_sync(FULL, seli[j], i2);
                const float* vr = WGV + ti * XS;
                a0[j] += pi * vr[lane];
                a1[j] += pi * vr[lane + 32];
            }
        }

        float rr0[2], rr1[2], sm1[2];
        #pragma unroll
        for (int j = 0; j < 2; j++) {
            rr0[j] = a0[j] + res0[j];
            rr1[j] = a1[j] + res1[j];
            sm1[j] = rr0[j] + rr1[j];
        }
        #pragma unroll
        for (int off = 16; off > 0; off >>= 1) {
            #pragma unroll
            for (int j = 0; j < 2; j++) sm1[j] += __shfl_xor_sync(FULL, sm1[j], off);
        }
        float d0[2], d1[2], sq[2];
        #pragma unroll
        for (int j = 0; j < 2; j++) {
            float mu = sm1[j] * (1.0f / 64.0f);
            d0[j] = rr0[j] - mu; d1[j] = rr1[j] - mu;
            sq[j] = d0[j]*d0[j] + d1[j]*d1[j];
        }
        #pragma unroll
        for (int off = 16; off > 0; off >>= 1) {
            #pragma unroll
            for (int j = 0; j < 2; j++) sq[j] += __shfl_xor_sync(FULL, sq[j], off);
        }
        #pragma unroll
        for (int j = 0; j < 2; j++) {
            float inv_sd = rsqrtf(sq[j] * (1.0f / 64.0f) + 1e-5f);
            float* ob = out_main + (((size_t)(b * Ss + sA + j)) * Nn + n) * Hh;
            ob[lane]      = d0[j] * inv_sd * sg[lane]      + sb[lane];
            ob[lane + 32] = d1[j] * inv_sd * sg[lane + 32] + sb[lane + 32];
        }
    }
}

extern "C" void kernel_launch(void* const* d_in, const int* in_sizes, int n_in,
                              void* d_out, int out_size) {
    const float* traffic = (const float*)d_in[0];
    const float* text    = (const float*)d_in[1];
    const float* Wq      = (const float*)d_in[2];
    const float* bq      = (const float*)d_in[3];
    const float* Wk      = (const float*)d_in[4];
    const float* bk      = (const float*)d_in[5];
    const float* Wv      = (const float*)d_in[6];
    const float* bv      = (const float*)d_in[7];
    const float* gamma   = (const float*)d_in[8];
    const float* beta    = (const float*)d_in[9];
    const int*   topk    = (n_in > 10) ? (const int*)d_in[10] : nullptr;

    float* out  = (float*)d_out;
    float* attn = out + (size_t)Bb * Ss * Nn * Hh;

    size_t smem = (size_t)SMEM_FLOATS * sizeof(float);   // 145152 B
    cudaFuncSetAttribute(fused_align_k, cudaFuncAttributeMaxDynamicSharedMemorySize, (int)smem);

    precompute_k<<<16, 256>>>(Wq, bq, Wk, bk);
    fused_align_k<<<Mm, NTH, smem>>>(traffic, text, Wv, bv, gamma, beta, topk, out, attn);
}

// round 12
// speedup vs baseline: 1.3499x; 1.3499x over previous
#include <cuda_runtime.h>
#include <stdint.h>
#include <math.h>

#define Bb 4
#define Ss 128
#define Nn 512
#define Hh 64
#define Mm 2048
#define XSTR 68
#define SSTR 132
#define NTH 1024

// smem float offsets (identical to R7)
#define F_XTR  0          // fp32 [128][68] residual + A of P GEMM
#define F_XTXH 8704       // tf32-hi [128][68]
#define F_XTXL 17408      // tf32-lo [128][68]
#define F_W    26112      // G_h[4352] G_l[4352] Wv_h[4352] Wv_l[4352]; P fp32 overlays first 8704
#define F_VSM  43520      // fp32 [128][68]
#define F_TAIL 52224      // rb128 cb128 sg64 sb64 sbv64
#define F_SC   8704       // scores [128][132] overlay Xtx after S GEMM
#define SMEM_FLOATS (F_TAIL + 448)

// ---------------- precomputed operands ----------------
__device__ float g_Gt[Hh*Hh];      // [c][h] = scale * sum_o Wq[o][h] Wk[o][c]
__device__ float g_u[Hh];
__device__ float g_w[Hh];
__device__ float g_c0;
__device__ __align__(16) float g_Wsplit[4*4352];  // G_h, G_l, Wv_h, Wv_l in [64][68] layout

__global__ void precompute_k(const float* __restrict__ Wq, const float* __restrict__ bq,
                             const float* __restrict__ Wk, const float* __restrict__ bk) {
    int gid = blockIdx.x * blockDim.x + threadIdx.x;
    const float scale = 0.125f;
    if (gid < Hh * Hh) {
        int c = gid >> 6, h = gid & 63;
        float s = 0.f;
        #pragma unroll 8
        for (int o = 0; o < Hh; o++) s += Wq[o*Hh + h] * Wk[o*Hh + c];
        g_Gt[gid] = s * scale;
    }
    if (gid < Hh) {
        float s = 0.f, t = 0.f;
        #pragma unroll 8
        for (int o = 0; o < Hh; o++) { s += Wq[o*Hh + gid] * bk[o]; t += Wk[o*Hh + gid] * bq[o]; }
        g_u[gid] = s * scale;
        g_w[gid] = t * scale;
    }
    if (gid == 0) {
        float s = 0.f;
        for (int o = 0; o < Hh; o++) s += bq[o] * bk[o];
        g_c0 = s * scale;
    }
}

__device__ __forceinline__ void tf32x2(float x, uint32_t& h, uint32_t& l) {
    asm("cvt.rna.tf32.f32 %0, %1;" : "=r"(h) : "f"(x));
    float r = x - __uint_as_float(h);
    asm("cvt.rna.tf32.f32 %0, %1;" : "=r"(l) : "f"(r));
}

__global__ void precompute_pack(const float* __restrict__ Wv) {
    int gid = blockIdx.x * blockDim.x + threadIdx.x;
    if (gid >= 2 * 4352) return;
    int mat = gid / 4352;
    int rem = gid % 4352;
    int r = rem / XSTR, c = rem % XSTR;
    float v = 0.f;
    if (c < 64) v = mat ? Wv[r*64 + c] : g_Gt[r*64 + c];
    uint32_t h, l;
    tf32x2(v, h, l);
    g_Wsplit[mat*8704 + rem]        = __uint_as_float(h);
    g_Wsplit[mat*8704 + 4352 + rem] = __uint_as_float(l);
}

// ---------------- mma helpers (identical to R7) ----------------
__device__ __forceinline__ void mma8(float c[4], const uint32_t a[4], uint32_t b0, uint32_t b1) {
    asm volatile(
        "mma.sync.aligned.m16n8k8.row.col.f32.tf32.tf32.f32 "
        "{%0,%1,%2,%3}, {%4,%5,%6,%7}, {%8,%9}, {%0,%1,%2,%3};"
        : "+f"(c[0]), "+f"(c[1]), "+f"(c[2]), "+f"(c[3])
        : "r"(a[0]), "r"(a[1]), "r"(a[2]), "r"(a[3]), "r"(b0), "r"(b1));
}

__device__ __forceinline__ void gemm_fly(const float* __restrict__ A,
                                         const float* __restrict__ Bh, const float* __restrict__ Bl,
                                         int mb, int n0, int lane, float acc[4][4]) {
    const int g = lane >> 2, q = lane & 3;
    const float* ar0 = A + (mb + g) * XSTR + q;
    const float* ar1 = A + (mb + g + 8) * XSTR + q;
    #pragma unroll
    for (int k0 = 0; k0 < 64; k0 += 8) {
        uint32_t ah[4], al[4];
        tf32x2(ar0[k0],   ah[0], al[0]);
        tf32x2(ar1[k0],   ah[1], al[1]);
        tf32x2(ar0[k0+4], ah[2], al[2]);
        tf32x2(ar1[k0+4], ah[3], al[3]);
        #pragma unroll
        for (int nt = 0; nt < 4; nt++) {
            int bi = (n0 + 8*nt + g) * XSTR + k0 + q;
            uint32_t b0h = __float_as_uint(Bh[bi]), b1h = __float_as_uint(Bh[bi+4]);
            uint32_t b0l = __float_as_uint(Bl[bi]), b1l = __float_as_uint(Bl[bi+4]);
            mma8(acc[nt], ah, b0h, b1h);
            mma8(acc[nt], ah, b0l, b1l);
            mma8(acc[nt], al, b0h, b1h);
        }
    }
}

__device__ __forceinline__ void gemm_ps(const float* __restrict__ Ah, const float* __restrict__ Al,
                                        const float* __restrict__ Bh, const float* __restrict__ Bl,
                                        int mb, int n0, int lane, float acc[4][4]) {
    const int g = lane >> 2, q = lane & 3;
    const int r0 = (mb + g) * XSTR + q, r1 = (mb + g + 8) * XSTR + q;
    #pragma unroll
    for (int k0 = 0; k0 < 64; k0 += 8) {
        uint32_t ah[4], al[4];
        ah[0] = __float_as_uint(Ah[r0 + k0]);   al[0] = __float_as_uint(Al[r0 + k0]);
        ah[1] = __float_as_uint(Ah[r1 + k0]);   al[1] = __float_as_uint(Al[r1 + k0]);
        ah[2] = __float_as_uint(Ah[r0 + k0+4]); al[2] = __float_as_uint(Al[r0 + k0+4]);
        ah[3] = __float_as_uint(Ah[r1 + k0+4]); al[3] = __float_as_uint(Al[r1 + k0+4]);
        #pragma unroll
        for (int nt = 0; nt < 4; nt++) {
            int bi = (n0 + 8*nt + g) * XSTR + k0 + q;
            uint32_t b0h = __float_as_uint(Bh[bi]), b1h = __float_as_uint(Bh[bi+4]);
            uint32_t b0l = __float_as_uint(Bl[bi]), b1l = __float_as_uint(Bl[bi+4]);
            mma8(acc[nt], ah, b0h, b1h);
            mma8(acc[nt], ah, b0l, b1l);
            mma8(acc[nt], al, b0h, b1h);
        }
    }
}

__device__ __forceinline__ unsigned f2mono(float v) {
    unsigned u = __float_as_uint(v);
    return (u & 0x80000000u) ? ~u : (u | 0x80000000u);
}
__device__ __forceinline__ float mono2f(unsigned k) {
    unsigned u = (k & 0x80000000u) ? (k ^ 0x80000000u) : ~k;
    return __uint_as_float(u);
}
// descending compare-exchange on (key, idx)
__device__ __forceinline__ void cas_desc(unsigned& ka, int& ia, unsigned& kb, int& ib) {
    if (ka < kb) {
        unsigned tk = ka; ka = kb; kb = tk;
        int ti = ia; ia = ib; ib = ti;
    }
}

extern __shared__ float smf[];
__global__ void __launch_bounds__(NTH, 1)
fused_align_k(const float* __restrict__ traffic, const float* __restrict__ text,
              const float* __restrict__ Wv, const float* __restrict__ bv,
              const float* __restrict__ gamma, const float* __restrict__ beta,
              const int* __restrict__ topk_p,
              float* __restrict__ out_main, float* __restrict__ out_attn) {
    float* xt_tr = smf + F_XTR;
    float* xtxh  = smf + F_XTXH;
    float* xtxl  = smf + F_XTXL;
    float* Wr    = smf + F_W;
    float* vsm   = smf + F_VSM;
    float* sc    = smf + F_SC;
    float* rb  = smf + F_TAIL;
    float* cb  = rb + 128;
    float* sg  = cb + 128;
    float* sb  = sg + 64;
    float* sbv = sb + 64;

    const int tid = threadIdx.x;
    const int lane = tid & 31;
    const int wrp = tid >> 5;
    const int m = blockIdx.x;
    const int b = m >> 9;
    const int n = m & (Nn - 1);

    const float* tr_base = traffic + ((size_t)b * Ss * Nn + n) * Hh;
    const float* tx_base = text    + ((size_t)b * Ss * Nn + n) * Hh;

    // ---- Stage 0 (identical to R7) ----
    for (int i = tid; i < 4352; i += NTH)
        ((uint4*)Wr)[i] = ((const uint4*)g_Wsplit)[i];
    #pragma unroll
    for (int it = 0; it < 2; it++) {
        int i = tid + it * NTH;
        int r = i >> 4, f = i & 15;
        float4 a  = *(const float4*)(tr_base + (size_t)r * Nn * Hh + f * 4);
        float4 bx = *(const float4*)(tx_base + (size_t)r * Nn * Hh + f * 4);
        *(float4*)(xt_tr + r * XSTR + f * 4) = a;
        uint32_t h0,l0,h1,l1,h2,l2,h3,l3;
        tf32x2(bx.x,h0,l0); tf32x2(bx.y,h1,l1); tf32x2(bx.z,h2,l2); tf32x2(bx.w,h3,l3);
        float4 hv, lv;
        hv.x=__uint_as_float(h0); hv.y=__uint_as_float(h1); hv.z=__uint_as_float(h2); hv.w=__uint_as_float(h3);
        lv.x=__uint_as_float(l0); lv.y=__uint_as_float(l1); lv.z=__uint_as_float(l2); lv.w=__uint_as_float(l3);
        *(float4*)(xtxh + r * XSTR + f * 4) = hv;
        *(float4*)(xtxl + r * XSTR + f * 4) = lv;
        float4 uu = *(const float4*)(g_u + f * 4);
        float4 ww = *(const float4*)(g_w + f * 4);
        float pr = a.x*uu.x + a.y*uu.y + a.z*uu.z + a.w*uu.w;
        float pc = bx.x*ww.x + bx.y*ww.y + bx.z*ww.z + bx.w*ww.w;
        #pragma unroll
        for (int o = 8; o > 0; o >>= 1) {
            pr += __shfl_xor_sync(0xffffffffu, pr, o);
            pc += __shfl_xor_sync(0xffffffffu, pc, o);
        }
        if (f == 0) { rb[r] = pr + g_c0; cb[r] = pc; }
    }
    if (tid < 64) { sg[tid] = gamma[tid]; sb[tid] = beta[tid]; sbv[tid] = bv[tid]; }
    __syncthreads();

    const int g = lane >> 2, q = lane & 3;

    // ---- Phase 1: P (warps 0-15) / V (warps 16-31) — identical to R7 ----
    float accPV[4][4];
    #pragma unroll
    for (int i = 0; i < 4; i++)
        #pragma unroll
        for (int j = 0; j < 4; j++) accPV[i][j] = 0.f;
    {
        int w2 = (wrp < 16) ? wrp : (wrp - 16);
        int mb = (w2 >> 1) * 16, n0 = (w2 & 1) * 32;
        if (wrp < 16) {
            gemm_fly(xt_tr, Wr, Wr + 4352, mb, n0, lane, accPV);
        } else {
            gemm_ps(xtxh, xtxl, Wr + 8704, Wr + 13056, mb, n0, lane, accPV);
            #pragma unroll
            for (int nt = 0; nt < 4; nt++) {
                int col = n0 + 8*nt + 2*q;
                float2 o0 = { accPV[nt][0] + sbv[col], accPV[nt][1] + sbv[col+1] };
                float2 o1 = { accPV[nt][2] + sbv[col], accPV[nt][3] + sbv[col+1] };
                *(float2*)(vsm + (mb + g) * XSTR + col)     = o0;
                *(float2*)(vsm + (mb + g + 8) * XSTR + col) = o1;
            }
        }
    }
    __syncthreads();
    if (wrp < 16) {
        int mb = (wrp >> 1) * 16, n0 = (wrp & 1) * 32;
        #pragma unroll
        for (int nt = 0; nt < 4; nt++) {
            int col = n0 + 8*nt + 2*q;
            float2 o0 = { accPV[nt][0], accPV[nt][1] };
            float2 o1 = { accPV[nt][2], accPV[nt][3] };
            *(float2*)(Wr + (mb + g) * XSTR + col)     = o0;
            *(float2*)(Wr + (mb + g + 8) * XSTR + col) = o1;
        }
    }
    __syncthreads();

    // ---- Phase 2: S GEMM (identical to R7) ----
    float accS[4][4];
    #pragma unroll
    for (int i = 0; i < 4; i++)
        #pragma unroll
        for (int j = 0; j < 4; j++) accS[i][j] = 0.f;
    const int smb = (wrp >> 2) * 16, sn0 = (wrp & 3) * 32;
    gemm_fly(Wr, xtxh, xtxl, smb, sn0, lane, accS);
    __syncthreads();
    #pragma unroll
    for (int nt = 0; nt < 4; nt++) {
        int col = sn0 + 8*nt + 2*q;
        float2 o0 = { accS[nt][0], accS[nt][1] };
        float2 o1 = { accS[nt][2], accS[nt][3] };
        *(float2*)(sc + (smb + g) * SSTR + col)     = o0;
        *(float2*)(sc + (smb + g + 8) * SSTR + col) = o1;
    }
    __syncthreads();

    // ---- Stage 3 (REWORKED): sorted shift-register top-k, float4 score/attn path ----
    int kk = 16;
    if (topk_p) { kk = topk_p[0]; if (kk < 1) kk = 1; if (kk > 32) kk = 32; }

    const int r0 = wrp * 4;
    float* attn_base = out_attn + (size_t)m * Ss * Ss;
    const unsigned FULL = 0xffffffffu;

    for (int ri = 0; ri < 4; ++ri) {
        const int s = r0 + ri;
        const float rbias = rb[s];
        // lane owns columns t = 4*lane + j (LDS.128, conflict-free)
        float4 sv  = *(const float4*)(sc + s * SSTR + 4 * lane);
        float4 cbv = *(const float4*)(cb + 4 * lane);
        float o0 = sv.x + rbias + cbv.x;
        float o1 = sv.y + rbias + cbv.y;
        float o2 = sv.z + rbias + cbv.z;
        float o3 = sv.w + rbias + cbv.w;
        unsigned k0 = f2mono(o0), k1 = f2mono(o1), k2 = f2mono(o2), k3 = f2mono(o3);

        // per-lane descending sort of 4 (key, global idx) pairs
        unsigned s0 = k0, s1 = k1, s2 = k2, s3 = k3;
        int i0 = 4*lane, i1 = 4*lane+1, i2r = 4*lane+2, i3 = 4*lane+3;
        cas_desc(s0, i0, s1, i1);
        cas_desc(s2, i2r, s3, i3);
        cas_desc(s0, i0, s2, i2r);
        cas_desc(s1, i1, s3, i3);
        cas_desc(s1, i1, s2, i2r);

        unsigned maxk = 0, thrk = 0, selk = 0; int seli = 0;
        for (int it = 0; it < kk; ++it) {
            unsigned mw = __reduce_max_sync(FULL, s0);
            unsigned ball = __ballot_sync(FULL, s0 == mw);
            int owner = __ffs(ball) - 1;
            int gidx = __shfl_sync(FULL, i0, owner);
            if (it == 0) maxk = mw;
            thrk = mw;
            if (lane == it) { selk = mw; seli = gidx; }
            if (lane == owner) {            // advance sorted list (shift registers)
                s0 = s1; s1 = s2; s2 = s3; s3 = 0;
                i0 = i1; i1 = i2r; i2r = i3;
            }
        }

        float maxv = mono2f(maxk);
        float e0 = (k0 >= thrk) ? __expf(o0 - maxv) : 0.f;
        float e1 = (k1 >= thrk) ? __expf(o1 - maxv) : 0.f;
        float e2 = (k2 >= thrk) ? __expf(o2 - maxv) : 0.f;
        float e3 = (k3 >= thrk) ? __expf(o3 - maxv) : 0.f;
        float z = e0 + e1 + e2 + e3;
        #pragma unroll
        for (int off = 16; off > 0; off >>= 1) z += __shfl_xor_sync(FULL, z, off);
        float inv = 1.0f / z;

        float4 st; st.x = e0 * inv; st.y = e1 * inv; st.z = e2 * inv; st.w = e3 * inv;
        *(float4*)(attn_base + (size_t)s * Ss + 4 * lane) = st;   // STG.128, coalesced

        float p = (lane < kk) ? __expf(mono2f(selk) - maxv) * inv : 0.f;
        float a0 = 0.f, a1 = 0.f;
        for (int i2 = 0; i2 < kk; i2++) {
            float pi = __shfl_sync(FULL, p, i2);
            int   ti = __shfl_sync(FULL, seli, i2);
            const float* vr = vsm + ti * XSTR;
            a0 += pi * vr[lane];
            a1 += pi * vr[lane + 32];
        }

        float rr0 = a0 + xt_tr[s * XSTR + lane];
        float rr1 = a1 + xt_tr[s * XSTR + lane + 32];
        float sm1 = rr0 + rr1;
        #pragma unroll
        for (int off = 16; off > 0; off >>= 1) sm1 += __shfl_xor_sync(FULL, sm1, off);
        float mu = sm1 * (1.0f / 64.0f);
        float d0 = rr0 - mu, d1 = rr1 - mu;
        float sq = d0 * d0 + d1 * d1;
        #pragma unroll
        for (int off = 16; off > 0; off >>= 1) sq += __shfl_xor_sync(FULL, sq, off);
        float inv_sd = rsqrtf(sq * (1.0f / 64.0f) + 1e-5f);

        float* ob = out_main + (((size_t)(b * Ss + s)) * Nn + n) * Hh;
        ob[lane]      = d0 * inv_sd * sg[lane]      + sb[lane];
        ob[lane + 32] = d1 * inv_sd * sg[lane + 32] + sb[lane + 32];
    }
}

extern "C" void kernel_launch(void* const* d_in, const int* in_sizes, int n_in,
                              void* d_out, int out_size) {
    const float* traffic = (const float*)d_in[0];
    const float* text    = (const float*)d_in[1];
    const float* Wq      = (const float*)d_in[2];
    const float* bq      = (const float*)d_in[3];
    const float* Wk      = (const float*)d_in[4];
    const float* bk      = (const float*)d_in[5];
    const float* Wv      = (const float*)d_in[6];
    const float* bv      = (const float*)d_in[7];
    const float* gamma   = (const float*)d_in[8];
    const float* beta    = (const float*)d_in[9];
    const int*   topk    = (n_in > 10) ? (const int*)d_in[10] : nullptr;

    float* out  = (float*)d_out;
    float* attn = out + (size_t)Bb * Ss * Nn * Hh;

    size_t smem = (size_t)SMEM_FLOATS * sizeof(float);
    cudaFuncSetAttribute(fused_align_k, cudaFuncAttributeMaxDynamicSharedMemorySize, (int)smem);

    precompute_k<<<16, 256>>>(Wq, bq, Wk, bk);
    precompute_pack<<<34, 256>>>(Wv);
    fused_align_k<<<Mm, NTH, smem>>>(traffic, text, Wv, bv, gamma, beta, topk, out, attn);
}

// round 13
// speedup vs baseline: 1.3641x; 1.0106x over previous
#include <cuda_runtime.h>
#include <stdint.h>
#include <math.h>

#define Bb 4
#define Ss 128
#define Nn 512
#define Hh 64
#define Mm 2048
#define XSTR 68
#define SSTR 132
#define NTH 1024

// smem float offsets (identical to R12)
#define F_XTR  0
#define F_XTXH 8704
#define F_XTXL 17408
#define F_W    26112
#define F_VSM  43520
#define F_TAIL 52224
#define F_SC   8704
#define SMEM_FLOATS (F_TAIL + 448)

// ---------------- precomputed operands ----------------
__device__ float g_Gt[Hh*Hh];
__device__ float g_u[Hh];
__device__ float g_w[Hh];
__device__ float g_c0;
__device__ __align__(16) float g_Wsplit[4*4352];

__global__ void precompute_k(const float* __restrict__ Wq, const float* __restrict__ bq,
                             const float* __restrict__ Wk, const float* __restrict__ bk) {
    int gid = blockIdx.x * blockDim.x + threadIdx.x;
    const float scale = 0.125f;
    if (gid < Hh * Hh) {
        int c = gid >> 6, h = gid & 63;
        float s = 0.f;
        #pragma unroll 8
        for (int o = 0; o < Hh; o++) s += Wq[o*Hh + h] * Wk[o*Hh + c];
        g_Gt[gid] = s * scale;
    }
    if (gid < Hh) {
        float s = 0.f, t = 0.f;
        #pragma unroll 8
        for (int o = 0; o < Hh; o++) { s += Wq[o*Hh + gid] * bk[o]; t += Wk[o*Hh + gid] * bq[o]; }
        g_u[gid] = s * scale;
        g_w[gid] = t * scale;
    }
    if (gid == 0) {
        float s = 0.f;
        for (int o = 0; o < Hh; o++) s += bq[o] * bk[o];
        g_c0 = s * scale;
    }
}

__device__ __forceinline__ void tf32x2(float x, uint32_t& h, uint32_t& l) {
    asm("cvt.rna.tf32.f32 %0, %1;" : "=r"(h) : "f"(x));
    float r = x - __uint_as_float(h);
    asm("cvt.rna.tf32.f32 %0, %1;" : "=r"(l) : "f"(r));
}

__global__ void precompute_pack(const float* __restrict__ Wv) {
    int gid = blockIdx.x * blockDim.x + threadIdx.x;
    if (gid >= 2 * 4352) return;
    int mat = gid / 4352;
    int rem = gid % 4352;
    int r = rem / XSTR, c = rem % XSTR;
    float v = 0.f;
    if (c < 64) v = mat ? Wv[r*64 + c] : g_Gt[r*64 + c];
    uint32_t h, l;
    tf32x2(v, h, l);
    g_Wsplit[mat*8704 + rem]        = __uint_as_float(h);
    g_Wsplit[mat*8704 + 4352 + rem] = __uint_as_float(l);
}

// ---------------- mma helpers (identical to R12) ----------------
__device__ __forceinline__ void mma8(float c[4], const uint32_t a[4], uint32_t b0, uint32_t b1) {
    asm volatile(
        "mma.sync.aligned.m16n8k8.row.col.f32.tf32.tf32.f32 "
        "{%0,%1,%2,%3}, {%4,%5,%6,%7}, {%8,%9}, {%0,%1,%2,%3};"
        : "+f"(c[0]), "+f"(c[1]), "+f"(c[2]), "+f"(c[3])
        : "r"(a[0]), "r"(a[1]), "r"(a[2]), "r"(a[3]), "r"(b0), "r"(b1));
}

__device__ __forceinline__ void gemm_fly(const float* __restrict__ A,
                                         const float* __restrict__ Bh, const float* __restrict__ Bl,
                                         int mb, int n0, int lane, float acc[4][4]) {
    const int g = lane >> 2, q = lane & 3;
    const float* ar0 = A + (mb + g) * XSTR + q;
    const float* ar1 = A + (mb + g + 8) * XSTR + q;
    #pragma unroll
    for (int k0 = 0; k0 < 64; k0 += 8) {
        uint32_t ah[4], al[4];
        tf32x2(ar0[k0],   ah[0], al[0]);
        tf32x2(ar1[k0],   ah[1], al[1]);
        tf32x2(ar0[k0+4], ah[2], al[2]);
        tf32x2(ar1[k0+4], ah[3], al[3]);
        #pragma unroll
        for (int nt = 0; nt < 4; nt++) {
            int bi = (n0 + 8*nt + g) * XSTR + k0 + q;
            uint32_t b0h = __float_as_uint(Bh[bi]), b1h = __float_as_uint(Bh[bi+4]);
            uint32_t b0l = __float_as_uint(Bl[bi]), b1l = __float_as_uint(Bl[bi+4]);
            mma8(acc[nt], ah, b0h, b1h);
            mma8(acc[nt], ah, b0l, b1l);
            mma8(acc[nt], al, b0h, b1h);
        }
    }
}

__device__ __forceinline__ void gemm_ps(const float* __restrict__ Ah, const float* __restrict__ Al,
                                        const float* __restrict__ Bh, const float* __restrict__ Bl,
                                        int mb, int n0, int lane, float acc[4][4]) {
    const int g = lane >> 2, q = lane & 3;
    const int r0 = (mb + g) * XSTR + q, r1 = (mb + g + 8) * XSTR + q;
    #pragma unroll
    for (int k0 = 0; k0 < 64; k0 += 8) {
        uint32_t ah[4], al[4];
        ah[0] = __float_as_uint(Ah[r0 + k0]);   al[0] = __float_as_uint(Al[r0 + k0]);
        ah[1] = __float_as_uint(Ah[r1 + k0]);   al[1] = __float_as_uint(Al[r1 + k0]);
        ah[2] = __float_as_uint(Ah[r0 + k0+4]); al[2] = __float_as_uint(Al[r0 + k0+4]);
        ah[3] = __float_as_uint(Ah[r1 + k0+4]); al[3] = __float_as_uint(Al[r1 + k0+4]);
        #pragma unroll
        for (int nt = 0; nt < 4; nt++) {
            int bi = (n0 + 8*nt + g) * XSTR + k0 + q;
            uint32_t b0h = __float_as_uint(Bh[bi]), b1h = __float_as_uint(Bh[bi+4]);
            uint32_t b0l = __float_as_uint(Bl[bi]), b1l = __float_as_uint(Bl[bi+4]);
            mma8(acc[nt], ah, b0h, b1h);
            mma8(acc[nt], ah, b0l, b1l);
            mma8(acc[nt], al, b0h, b1h);
        }
    }
}

__device__ __forceinline__ unsigned f2mono(float v) {
    unsigned u = __float_as_uint(v);
    return (u & 0x80000000u) ? ~u : (u | 0x80000000u);
}
__device__ __forceinline__ float mono2f(unsigned k) {
    unsigned u = (k & 0x80000000u) ? (k ^ 0x80000000u) : ~k;
    return __uint_as_float(u);
}
__device__ __forceinline__ void cas_desc(unsigned& ka, int& ia, unsigned& kb, int& ib) {
    if (ka < kb) {
        unsigned tk = ka; ka = kb; kb = tk;
        int ti = ia; ia = ib; ib = ti;
    }
}

extern __shared__ float smf[];
__global__ void __launch_bounds__(NTH, 1)
fused_align_k(const float* __restrict__ traffic, const float* __restrict__ text,
              const float* __restrict__ Wv, const float* __restrict__ bv,
              const float* __restrict__ gamma, const float* __restrict__ beta,
              const int* __restrict__ topk_p,
              float* __restrict__ out_main, float* __restrict__ out_attn) {
    float* xt_tr = smf + F_XTR;
    float* xtxh  = smf + F_XTXH;
    float* xtxl  = smf + F_XTXL;
    float* Wr    = smf + F_W;
    float* vsm   = smf + F_VSM;
    float* sc    = smf + F_SC;
    float* rb  = smf + F_TAIL;
    float* cb  = rb + 128;
    float* sg  = cb + 128;
    float* sb  = sg + 64;
    float* sbv = sb + 64;

    const int tid = threadIdx.x;
    const int lane = tid & 31;
    const int wrp = tid >> 5;
    const int m = blockIdx.x;
    const int b = m >> 9;
    const int n = m & (Nn - 1);

    const float* tr_base = traffic + ((size_t)b * Ss * Nn + n) * Hh;
    const float* tx_base = text    + ((size_t)b * Ss * Nn + n) * Hh;

    // ---- Stage 0 (identical to R12) ----
    for (int i = tid; i < 4352; i += NTH)
        ((uint4*)Wr)[i] = ((const uint4*)g_Wsplit)[i];
    #pragma unroll
    for (int it = 0; it < 2; it++) {
        int i = tid + it * NTH;
        int r = i >> 4, f = i & 15;
        float4 a  = *(const float4*)(tr_base + (size_t)r * Nn * Hh + f * 4);
        float4 bx = *(const float4*)(tx_base + (size_t)r * Nn * Hh + f * 4);
        *(float4*)(xt_tr + r * XSTR + f * 4) = a;
        uint32_t h0,l0,h1,l1,h2,l2,h3,l3;
        tf32x2(bx.x,h0,l0); tf32x2(bx.y,h1,l1); tf32x2(bx.z,h2,l2); tf32x2(bx.w,h3,l3);
        float4 hv, lv;
        hv.x=__uint_as_float(h0); hv.y=__uint_as_float(h1); hv.z=__uint_as_float(h2); hv.w=__uint_as_float(h3);
        lv.x=__uint_as_float(l0); lv.y=__uint_as_float(l1); lv.z=__uint_as_float(l2); lv.w=__uint_as_float(l3);
        *(float4*)(xtxh + r * XSTR + f * 4) = hv;
        *(float4*)(xtxl + r * XSTR + f * 4) = lv;
        float4 uu = *(const float4*)(g_u + f * 4);
        float4 ww = *(const float4*)(g_w + f * 4);
        float pr = a.x*uu.x + a.y*uu.y + a.z*uu.z + a.w*uu.w;
        float pc = bx.x*ww.x + bx.y*ww.y + bx.z*ww.z + bx.w*ww.w;
        #pragma unroll
        for (int o = 8; o > 0; o >>= 1) {
            pr += __shfl_xor_sync(0xffffffffu, pr, o);
            pc += __shfl_xor_sync(0xffffffffu, pc, o);
        }
        if (f == 0) { rb[r] = pr + g_c0; cb[r] = pc; }
    }
    if (tid < 64) { sg[tid] = gamma[tid]; sb[tid] = beta[tid]; sbv[tid] = bv[tid]; }
    __syncthreads();

    const int g = lane >> 2, q = lane & 3;

    // ---- Phase 1: P (warps 0-15) / V (warps 16-31) — identical to R12 ----
    float accPV[4][4];
    #pragma unroll
    for (int i = 0; i < 4; i++)
        #pragma unroll
        for (int j = 0; j < 4; j++) accPV[i][j] = 0.f;
    {
        int w2 = (wrp < 16) ? wrp : (wrp - 16);
        int mb = (w2 >> 1) * 16, n0 = (w2 & 1) * 32;
        if (wrp < 16) {
            gemm_fly(xt_tr, Wr, Wr + 4352, mb, n0, lane, accPV);
        } else {
            gemm_ps(xtxh, xtxl, Wr + 8704, Wr + 13056, mb, n0, lane, accPV);
            #pragma unroll
            for (int nt = 0; nt < 4; nt++) {
                int col = n0 + 8*nt + 2*q;
                float2 o0 = { accPV[nt][0] + sbv[col], accPV[nt][1] + sbv[col+1] };
                float2 o1 = { accPV[nt][2] + sbv[col], accPV[nt][3] + sbv[col+1] };
                *(float2*)(vsm + (mb + g) * XSTR + col)     = o0;
                *(float2*)(vsm + (mb + g + 8) * XSTR + col) = o1;
            }
        }
    }
    __syncthreads();
    if (wrp < 16) {
        int mb = (wrp >> 1) * 16, n0 = (wrp & 1) * 32;
        #pragma unroll
        for (int nt = 0; nt < 4; nt++) {
            int col = n0 + 8*nt + 2*q;
            float2 o0 = { accPV[nt][0], accPV[nt][1] };
            float2 o1 = { accPV[nt][2], accPV[nt][3] };
            *(float2*)(Wr + (mb + g) * XSTR + col)     = o0;
            *(float2*)(Wr + (mb + g + 8) * XSTR + col) = o1;
        }
    }
    __syncthreads();

    // ---- Phase 2: S GEMM (identical to R12) ----
    float accS[4][4];
    #pragma unroll
    for (int i = 0; i < 4; i++)
        #pragma unroll
        for (int j = 0; j < 4; j++) accS[i][j] = 0.f;
    const int smb = (wrp >> 2) * 16, sn0 = (wrp & 3) * 32;
    gemm_fly(Wr, xtxh, xtxl, smb, sn0, lane, accS);
    __syncthreads();
    #pragma unroll
    for (int nt = 0; nt < 4; nt++) {
        int col = sn0 + 8*nt + 2*q;
        float2 o0 = { accS[nt][0], accS[nt][1] };
        float2 o1 = { accS[nt][2], accS[nt][3] };
        *(float2*)(sc + (smb + g) * SSTR + col)     = o0;
        *(float2*)(sc + (smb + g + 8) * SSTR + col) = o1;
    }
    __syncthreads();

    // ---- Stage 3: 2-row interleaved sorted shift-register top-k + softmax + AV + LN ----
    int kk = 16;
    if (topk_p) { kk = topk_p[0]; if (kk < 1) kk = 1; if (kk > 32) kk = 32; }

    const int r0 = wrp * 4;
    float* attn_base = out_attn + (size_t)m * Ss * Ss;
    const unsigned FULL = 0xffffffffu;

    #pragma unroll
    for (int rp = 0; rp < 2; rp++) {
        const int sA = r0 + 2*rp;
        float o[2][4];
        unsigned s0[2], s1[2], s2[2], s3[2], ip[2];
        #pragma unroll
        for (int j = 0; j < 2; j++) {
            const int s = sA + j;
            float4 sv  = *(const float4*)(sc + s * SSTR + 4 * lane);
            float4 cbv = *(const float4*)(cb + 4 * lane);
            const float rbias = rb[s];
            o[j][0] = sv.x + rbias + cbv.x;
            o[j][1] = sv.y + rbias + cbv.y;
            o[j][2] = sv.z + rbias + cbv.z;
            o[j][3] = sv.w + rbias + cbv.w;
            unsigned a0k = f2mono(o[j][0]), a1k = f2mono(o[j][1]);
            unsigned a2k = f2mono(o[j][2]), a3k = f2mono(o[j][3]);
            // per-lane descending sort of 4 (key, slot) pairs
            unsigned t0 = a0k, t1 = a1k, t2 = a2k, t3 = a3k;
            int j0 = 0, j1 = 1, j2 = 2, j3 = 3;
            cas_desc(t0, j0, t1, j1);
            cas_desc(t2, j2, t3, j3);
            cas_desc(t0, j0, t2, j2);
            cas_desc(t1, j1, t3, j3);
            cas_desc(t1, j1, t2, j2);
            s0[j] = t0; s1[j] = t1; s2[j] = t2; s3[j] = t3;
            // pack global column indices (4*lane+slot, <=127) as 4 bytes, head in low byte
            ip[j] = (unsigned)(4*lane + j0) | ((unsigned)(4*lane + j1) << 8)
                  | ((unsigned)(4*lane + j2) << 16) | ((unsigned)(4*lane + j3) << 24);
        }

        unsigned maxk[2], thrk[2], selk[2]; int seli[2];
        #pragma unroll
        for (int j = 0; j < 2; j++) { maxk[j] = 0; thrk[j] = 0; selk[j] = 0; seli[j] = 0; }

        for (int it = 0; it < kk; ++it) {
            unsigned mw0 = __reduce_max_sync(FULL, s0[0]);
            unsigned mw1 = __reduce_max_sync(FULL, s0[1]);
            bool self0 = (s0[0] == mw0);
            bool self1 = (s0[1] == mw1);
            // winner-index recording (off the next-REDUX critical path)
            unsigned bl0 = __ballot_sync(FULL, self0);
            unsigned bl1 = __ballot_sync(FULL, self1);
            int gi0 = (int)(__shfl_sync(FULL, ip[0], __ffs(bl0) - 1) & 0xffu);
            int gi1 = (int)(__shfl_sync(FULL, ip[1], __ffs(bl1) - 1) & 0xffu);
            if (it == 0) { maxk[0] = mw0; maxk[1] = mw1; }
            thrk[0] = mw0; thrk[1] = mw1;
            if (lane == it) { selk[0] = mw0; seli[0] = gi0; selk[1] = mw1; seli[1] = gi1; }
            // self-determined advance (exact keys: ties are measure-zero)
            if (self0) { s0[0] = s1[0]; s1[0] = s2[0]; s2[0] = s3[0]; s3[0] = 0; ip[0] >>= 8; }
            if (self1) { s0[1] = s1[1]; s1[1] = s2[1]; s2[1] = s3[1]; s3[1] = 0; ip[1] >>= 8; }
        }

        float maxv[2], z[2], inv[2], e[2][4];
        #pragma unroll
        for (int j = 0; j < 2; j++) {
            maxv[j] = mono2f(maxk[j]);
            #pragma unroll
            for (int t = 0; t < 4; t++)
                e[j][t] = (f2mono(o[j][t]) >= thrk[j]) ? __expf(o[j][t] - maxv[j]) : 0.f;
            z[j] = e[j][0] + e[j][1] + e[j][2] + e[j][3];
        }
        #pragma unroll
        for (int off = 16; off > 0; off >>= 1) {
            z[0] += __shfl_xor_sync(FULL, z[0], off);
            z[1] += __shfl_xor_sync(FULL, z[1], off);
        }
        #pragma unroll
        for (int j = 0; j < 2; j++) {
            inv[j] = 1.0f / z[j];
            float4 st;
            st.x = e[j][0] * inv[j]; st.y = e[j][1] * inv[j];
            st.z = e[j][2] * inv[j]; st.w = e[j][3] * inv[j];
            *(float4*)(attn_base + (size_t)(sA + j) * Ss + 4 * lane) = st;
        }

        float p[2];
        #pragma unroll
        for (int j = 0; j < 2; j++)
            p[j] = (lane < kk) ? __expf(mono2f(selk[j]) - maxv[j]) * inv[j] : 0.f;

        float a0[2] = {0.f, 0.f}, a1[2] = {0.f, 0.f};
        for (int i2 = 0; i2 < kk; i2++) {
            float pi0 = __shfl_sync(FULL, p[0], i2);
            int   ti0 = __shfl_sync(FULL, seli[0], i2);
            float pi1 = __shfl_sync(FULL, p[1], i2);
            int   ti1 = __shfl_sync(FULL, seli[1], i2);
            const float* vr0 = vsm + ti0 * XSTR;
            const float* vr1 = vsm + ti1 * XSTR;
            a0[0] += pi0 * vr0[lane];
            a1[0] += pi0 * vr0[lane + 32];
            a0[1] += pi1 * vr1[lane];
            a1[1] += pi1 * vr1[lane + 32];
        }

        float rr0[2], rr1[2], sm1[2];
        #pragma unroll
        for (int j = 0; j < 2; j++) {
            rr0[j] = a0[j] + xt_tr[(sA + j) * XSTR + lane];
            rr1[j] = a1[j] + xt_tr[(sA + j) * XSTR + lane + 32];
            sm1[j] = rr0[j] + rr1[j];
        }
        #pragma unroll
        for (int off = 16; off > 0; off >>= 1) {
            sm1[0] += __shfl_xor_sync(FULL, sm1[0], off);
            sm1[1] += __shfl_xor_sync(FULL, sm1[1], off);
        }
        float d0[2], d1[2], sq[2];
        #pragma unroll
        for (int j = 0; j < 2; j++) {
            float mu = sm1[j] * (1.0f / 64.0f);
            d0[j] = rr0[j] - mu; d1[j] = rr1[j] - mu;
            sq[j] = d0[j]*d0[j] + d1[j]*d1[j];
        }
        #pragma unroll
        for (int off = 16; off > 0; off >>= 1) {
            sq[0] += __shfl_xor_sync(FULL, sq[0], off);
            sq[1] += __shfl_xor_sync(FULL, sq[1], off);
        }
        #pragma unroll
        for (int j = 0; j < 2; j++) {
            float inv_sd = rsqrtf(sq[j] * (1.0f / 64.0f) + 1e-5f);
            float* ob = out_main + (((size_t)(b * Ss + sA + j)) * Nn + n) * Hh;
            ob[lane]      = d0[j] * inv_sd * sg[lane]      + sb[lane];
            ob[lane + 32] = d1[j] * inv_sd * sg[lane + 32] + sb[lane + 32];
        }
    }
}

extern "C" void kernel_launch(void* const* d_in, const int* in_sizes, int n_in,
                              void* d_out, int out_size) {
    const float* traffic = (const float*)d_in[0];
    const float* text    = (const float*)d_in[1];
    const float* Wq      = (const float*)d_in[2];
    const float* bq      = (const float*)d_in[3];
    const float* Wk      = (const float*)d_in[4];
    const float* bk      = (const float*)d_in[5];
    const float* Wv      = (const float*)d_in[6];
    const float* bv      = (const float*)d_in[7];
    const float* gamma   = (const float*)d_in[8];
    const float* beta    = (const float*)d_in[9];
    const int*   topk    = (n_in > 10) ? (const int*)d_in[10] : nullptr;

    float* out  = (float*)d_out;
    float* attn = out + (size_t)Bb * Ss * Nn * Hh;

    size_t smem = (size_t)SMEM_FLOATS * sizeof(float);
    cudaFuncSetAttribute(fused_align_k, cudaFuncAttributeMaxDynamicSharedMemorySize, (int)smem);

    precompute_k<<<16, 256>>>(Wq, bq, Wk, bk);
    precompute_pack<<<34, 256>>>(Wv);
    fused_align_k<<<Mm, NTH, smem>>>(traffic, text, Wv, bv, gamma, beta, topk, out, attn);
}

// round 14
// speedup vs baseline: 1.4546x; 1.0663x over previous
#include <cuda_runtime.h>
#include <stdint.h>
#include <math.h>

#define Bb 4
#define Ss 128
#define Nn 512
#define Hh 64
#define Mm 2048
#define XSTR 68
#define SSTR 132
#define NTH 1024

// smem float offsets (identical to R12/R13)
#define F_XTR  0
#define F_XTXH 8704
#define F_XTXL 17408
#define F_W    26112
#define F_VSM  43520
#define F_TAIL 52224
#define F_SC   8704
#define SMEM_FLOATS (F_TAIL + 448)

// ---------------- precomputed operands ----------------
__device__ float g_Gt[Hh*Hh];
__device__ float g_u[Hh];
__device__ float g_w[Hh];
__device__ float g_c0;
__device__ __align__(16) float g_Wsplit[4*4352];

__global__ void precompute_k(const float* __restrict__ Wq, const float* __restrict__ bq,
                             const float* __restrict__ Wk, const float* __restrict__ bk) {
    int gid = blockIdx.x * blockDim.x + threadIdx.x;
    const float scale = 0.125f;
    if (gid < Hh * Hh) {
        int c = gid >> 6, h = gid & 63;
        float s = 0.f;
        #pragma unroll 8
        for (int o = 0; o < Hh; o++) s += Wq[o*Hh + h] * Wk[o*Hh + c];
        g_Gt[gid] = s * scale;
    }
    if (gid < Hh) {
        float s = 0.f, t = 0.f;
        #pragma unroll 8
        for (int o = 0; o < Hh; o++) { s += Wq[o*Hh + gid] * bk[o]; t += Wk[o*Hh + gid] * bq[o]; }
        g_u[gid] = s * scale;
        g_w[gid] = t * scale;
    }
    if (gid == 0) {
        float s = 0.f;
        for (int o = 0; o < Hh; o++) s += bq[o] * bk[o];
        g_c0 = s * scale;
    }
}

__device__ __forceinline__ void tf32x2(float x, uint32_t& h, uint32_t& l) {
    asm("cvt.rna.tf32.f32 %0, %1;" : "=r"(h) : "f"(x));
    float r = x - __uint_as_float(h);
    asm("cvt.rna.tf32.f32 %0, %1;" : "=r"(l) : "f"(r));
}

__global__ void precompute_pack(const float* __restrict__ Wv) {
    int gid = blockIdx.x * blockDim.x + threadIdx.x;
    if (gid >= 2 * 4352) return;
    int mat = gid / 4352;
    int rem = gid % 4352;
    int r = rem / XSTR, c = rem % XSTR;
    float v = 0.f;
    if (c < 64) v = mat ? Wv[r*64 + c] : g_Gt[r*64 + c];
    uint32_t h, l;
    tf32x2(v, h, l);
    g_Wsplit[mat*8704 + rem]        = __uint_as_float(h);
    g_Wsplit[mat*8704 + 4352 + rem] = __uint_as_float(l);
}

// ---------------- mma helpers (identical to R12) ----------------
__device__ __forceinline__ void mma8(float c[4], const uint32_t a[4], uint32_t b0, uint32_t b1) {
    asm volatile(
        "mma.sync.aligned.m16n8k8.row.col.f32.tf32.tf32.f32 "
        "{%0,%1,%2,%3}, {%4,%5,%6,%7}, {%8,%9}, {%0,%1,%2,%3};"
        : "+f"(c[0]), "+f"(c[1]), "+f"(c[2]), "+f"(c[3])
        : "r"(a[0]), "r"(a[1]), "r"(a[2]), "r"(a[3]), "r"(b0), "r"(b1));
}

__device__ __forceinline__ void gemm_fly(const float* __restrict__ A,
                                         const float* __restrict__ Bh, const float* __restrict__ Bl,
                                         int mb, int n0, int lane, float acc[4][4]) {
    const int g = lane >> 2, q = lane & 3;
    const float* ar0 = A + (mb + g) * XSTR + q;
    const float* ar1 = A + (mb + g + 8) * XSTR + q;
    #pragma unroll
    for (int k0 = 0; k0 < 64; k0 += 8) {
        uint32_t ah[4], al[4];
        tf32x2(ar0[k0],   ah[0], al[0]);
        tf32x2(ar1[k0],   ah[1], al[1]);
        tf32x2(ar0[k0+4], ah[2], al[2]);
        tf32x2(ar1[k0+4], ah[3], al[3]);
        #pragma unroll
        for (int nt = 0; nt < 4; nt++) {
            int bi = (n0 + 8*nt + g) * XSTR + k0 + q;
            uint32_t b0h = __float_as_uint(Bh[bi]), b1h = __float_as_uint(Bh[bi+4]);
            uint32_t b0l = __float_as_uint(Bl[bi]), b1l = __float_as_uint(Bl[bi+4]);
            mma8(acc[nt], ah, b0h, b1h);
            mma8(acc[nt], ah, b0l, b1l);
            mma8(acc[nt], al, b0h, b1h);
        }
    }
}

__device__ __forceinline__ void gemm_ps(const float* __restrict__ Ah, const float* __restrict__ Al,
                                        const float* __restrict__ Bh, const float* __restrict__ Bl,
                                        int mb, int n0, int lane, float acc[4][4]) {
    const int g = lane >> 2, q = lane & 3;
    const int r0 = (mb + g) * XSTR + q, r1 = (mb + g + 8) * XSTR + q;
    #pragma unroll
    for (int k0 = 0; k0 < 64; k0 += 8) {
        uint32_t ah[4], al[4];
        ah[0] = __float_as_uint(Ah[r0 + k0]);   al[0] = __float_as_uint(Al[r0 + k0]);
        ah[1] = __float_as_uint(Ah[r1 + k0]);   al[1] = __float_as_uint(Al[r1 + k0]);
        ah[2] = __float_as_uint(Ah[r0 + k0+4]); al[2] = __float_as_uint(Al[r0 + k0+4]);
        ah[3] = __float_as_uint(Ah[r1 + k0+4]); al[3] = __float_as_uint(Al[r1 + k0+4]);
        #pragma unroll
        for (int nt = 0; nt < 4; nt++) {
            int bi = (n0 + 8*nt + g) * XSTR + k0 + q;
            uint32_t b0h = __float_as_uint(Bh[bi]), b1h = __float_as_uint(Bh[bi+4]);
            uint32_t b0l = __float_as_uint(Bl[bi]), b1l = __float_as_uint(Bl[bi+4]);
            mma8(acc[nt], ah, b0h, b1h);
            mma8(acc[nt], ah, b0l, b1l);
            mma8(acc[nt], al, b0h, b1h);
        }
    }
}

__device__ __forceinline__ unsigned f2mono(float v) {
    unsigned u = __float_as_uint(v);
    return (u & 0x80000000u) ? ~u : (u | 0x80000000u);
}
__device__ __forceinline__ float mono2f(unsigned k) {
    unsigned u = (k & 0x80000000u) ? (k ^ 0x80000000u) : ~k;
    return __uint_as_float(u);
}

extern __shared__ float smf[];
__global__ void __launch_bounds__(NTH, 1)
fused_align_k(const float* __restrict__ traffic, const float* __restrict__ text,
              const float* __restrict__ Wv, const float* __restrict__ bv,
              const float* __restrict__ gamma, const float* __restrict__ beta,
              const int* __restrict__ topk_p,
              float* __restrict__ out_main, float* __restrict__ out_attn) {
    float* xt_tr = smf + F_XTR;
    float* xtxh  = smf + F_XTXH;
    float* xtxl  = smf + F_XTXL;
    float* Wr    = smf + F_W;
    float* vsm   = smf + F_VSM;
    float* sc    = smf + F_SC;
    float* rb  = smf + F_TAIL;
    float* cb  = rb + 128;
    float* sg  = cb + 128;
    float* sb  = sg + 64;
    float* sbv = sb + 64;

    const int tid = threadIdx.x;
    const int lane = tid & 31;
    const int wrp = tid >> 5;
    const int m = blockIdx.x;
    const int b = m >> 9;
    const int n = m & (Nn - 1);

    const float* tr_base = traffic + ((size_t)b * Ss * Nn + n) * Hh;
    const float* tx_base = text    + ((size_t)b * Ss * Nn + n) * Hh;

    // ---- Stage 0 (identical to R12) ----
    for (int i = tid; i < 4352; i += NTH)
        ((uint4*)Wr)[i] = ((const uint4*)g_Wsplit)[i];
    #pragma unroll
    for (int it = 0; it < 2; it++) {
        int i = tid + it * NTH;
        int r = i >> 4, f = i & 15;
        float4 a  = *(const float4*)(tr_base + (size_t)r * Nn * Hh + f * 4);
        float4 bx = *(const float4*)(tx_base + (size_t)r * Nn * Hh + f * 4);
        *(float4*)(xt_tr + r * XSTR + f * 4) = a;
        uint32_t h0,l0,h1,l1,h2,l2,h3,l3;
        tf32x2(bx.x,h0,l0); tf32x2(bx.y,h1,l1); tf32x2(bx.z,h2,l2); tf32x2(bx.w,h3,l3);
        float4 hv, lv;
        hv.x=__uint_as_float(h0); hv.y=__uint_as_float(h1); hv.z=__uint_as_float(h2); hv.w=__uint_as_float(h3);
        lv.x=__uint_as_float(l0); lv.y=__uint_as_float(l1); lv.z=__uint_as_float(l2); lv.w=__uint_as_float(l3);
        *(float4*)(xtxh + r * XSTR + f * 4) = hv;
        *(float4*)(xtxl + r * XSTR + f * 4) = lv;
        float4 uu = *(const float4*)(g_u + f * 4);
        float4 ww = *(const float4*)(g_w + f * 4);
        float pr = a.x*uu.x + a.y*uu.y + a.z*uu.z + a.w*uu.w;
        float pc = bx.x*ww.x + bx.y*ww.y + bx.z*ww.z + bx.w*ww.w;
        #pragma unroll
        for (int o = 8; o > 0; o >>= 1) {
            pr += __shfl_xor_sync(0xffffffffu, pr, o);
            pc += __shfl_xor_sync(0xffffffffu, pc, o);
        }
        if (f == 0) { rb[r] = pr + g_c0; cb[r] = pc; }
    }
    if (tid < 64) { sg[tid] = gamma[tid]; sb[tid] = beta[tid]; sbv[tid] = bv[tid]; }
    __syncthreads();

    const int g = lane >> 2, q = lane & 3;

    // ---- Phase 1: P (warps 0-15) / V (warps 16-31) — identical to R12 ----
    float accPV[4][4];
    #pragma unroll
    for (int i = 0; i < 4; i++)
        #pragma unroll
        for (int j = 0; j < 4; j++) accPV[i][j] = 0.f;
    {
        int w2 = (wrp < 16) ? wrp : (wrp - 16);
        int mb = (w2 >> 1) * 16, n0 = (w2 & 1) * 32;
        if (wrp < 16) {
            gemm_fly(xt_tr, Wr, Wr + 4352, mb, n0, lane, accPV);
        } else {
            gemm_ps(xtxh, xtxl, Wr + 8704, Wr + 13056, mb, n0, lane, accPV);
            #pragma unroll
            for (int nt = 0; nt < 4; nt++) {
                int col = n0 + 8*nt + 2*q;
                float2 o0 = { accPV[nt][0] + sbv[col], accPV[nt][1] + sbv[col+1] };
                float2 o1 = { accPV[nt][2] + sbv[col], accPV[nt][3] + sbv[col+1] };
                *(float2*)(vsm + (mb + g) * XSTR + col)     = o0;
                *(float2*)(vsm + (mb + g + 8) * XSTR + col) = o1;
            }
        }
    }
    __syncthreads();
    if (wrp < 16) {
        int mb = (wrp >> 1) * 16, n0 = (wrp & 1) * 32;
        #pragma unroll
        for (int nt = 0; nt < 4; nt++) {
            int col = n0 + 8*nt + 2*q;
            float2 o0 = { accPV[nt][0], accPV[nt][1] };
            float2 o1 = { accPV[nt][2], accPV[nt][3] };
            *(float2*)(Wr + (mb + g) * XSTR + col)     = o0;
            *(float2*)(Wr + (mb + g + 8) * XSTR + col) = o1;
        }
    }
    __syncthreads();

    // ---- Phase 2: S GEMM (identical to R12) ----
    float accS[4][4];
    #pragma unroll
    for (int i = 0; i < 4; i++)
        #pragma unroll
        for (int j = 0; j < 4; j++) accS[i][j] = 0.f;
    const int smb = (wrp >> 2) * 16, sn0 = (wrp & 3) * 32;
    gemm_fly(Wr, xtxh, xtxl, smb, sn0, lane, accS);
    __syncthreads();
    #pragma unroll
    for (int nt = 0; nt < 4; nt++) {
        int col = sn0 + 8*nt + 2*q;
        float2 o0 = { accS[nt][0], accS[nt][1] };
        float2 o1 = { accS[nt][2], accS[nt][3] };
        *(float2*)(sc + (smb + g) * SSTR + col)     = o0;
        *(float2*)(sc + (smb + g + 8) * SSTR + col) = o1;
    }
    __syncthreads();

    // ---- Stage 3: minimal top-k (threshold only, exact single-pop) + post-hoc list AV ----
    int kk = 16;
    if (topk_p) { kk = topk_p[0]; if (kk < 1) kk = 1; if (kk > 32) kk = 32; }

    const int r0 = wrp * 4;
    float* attn_base = out_attn + (size_t)m * Ss * Ss;
    const unsigned FULL = 0xffffffffu;

    #pragma unroll
    for (int rp = 0; rp < 2; rp++) {
        const int sA = r0 + 2*rp;
        float o[2][4];
        unsigned kx[2][4];
        unsigned s0[2], s1[2], s2[2], s3[2];
        #pragma unroll
        for (int j = 0; j < 2; j++) {
            const int s = sA + j;
            float4 sv  = *(const float4*)(sc + s * SSTR + 4 * lane);
            float4 cbv = *(const float4*)(cb + 4 * lane);
            const float rbias = rb[s];
            o[j][0] = sv.x + rbias + cbv.x;
            o[j][1] = sv.y + rbias + cbv.y;
            o[j][2] = sv.z + rbias + cbv.z;
            o[j][3] = sv.w + rbias + cbv.w;
            #pragma unroll
            for (int t = 0; t < 4; t++) kx[j][t] = f2mono(o[j][t]);
            // keys-only descending sort (5 min/max pairs)
            unsigned t0 = kx[j][0], t1 = kx[j][1], t2 = kx[j][2], t3 = kx[j][3], u;
            u = max(t0,t1); t1 = min(t0,t1); t0 = u;
            u = max(t2,t3); t3 = min(t2,t3); t2 = u;
            u = max(t0,t2); t2 = min(t0,t2); t0 = u;
            u = max(t1,t3); t3 = min(t1,t3); t1 = u;
            u = max(t1,t2); t2 = min(t1,t2); t1 = u;
            s0[j] = t0; s1[j] = t1; s2[j] = t2; s3[j] = t3;
        }

        unsigned maxk[2] = {0, 0}, thrk[2] = {0, 0};
        for (int it = 0; it < kk; ++it) {
            unsigned mw0 = __reduce_max_sync(FULL, s0[0]);
            unsigned mw1 = __reduce_max_sync(FULL, s0[1]);
            unsigned bl0 = __ballot_sync(FULL, s0[0] == mw0);
            unsigned bl1 = __ballot_sync(FULL, s0[1] == mw1);
            if (it == 0) { maxk[0] = mw0; maxk[1] = mw1; }
            thrk[0] = mw0; thrk[1] = mw1;
            // exact single pop: lowest lane holding the max
            if (lane == __ffs(bl0) - 1) { s0[0] = s1[0]; s1[0] = s2[0]; s2[0] = s3[0]; s3[0] = 0; }
            if (lane == __ffs(bl1) - 1) { s0[1] = s1[1]; s1[1] = s2[1]; s2[1] = s3[1]; s3[1] = 0; }
        }

        // softmax + attn write
        float maxv[2], z[2], inv[2], st[2][4];
        #pragma unroll
        for (int j = 0; j < 2; j++) {
            maxv[j] = mono2f(maxk[j]);
            #pragma unroll
            for (int t = 0; t < 4; t++)
                st[j][t] = (kx[j][t] >= thrk[j]) ? __expf(o[j][t] - maxv[j]) : 0.f;
            z[j] = st[j][0] + st[j][1] + st[j][2] + st[j][3];
        }
        #pragma unroll
        for (int off = 16; off > 0; off >>= 1) {
            z[0] += __shfl_xor_sync(FULL, z[0], off);
            z[1] += __shfl_xor_sync(FULL, z[1], off);
        }
        #pragma unroll
        for (int j = 0; j < 2; j++) {
            inv[j] = 1.0f / z[j];
            #pragma unroll
            for (int t = 0; t < 4; t++) st[j][t] *= inv[j];
            float4 sv4; sv4.x = st[j][0]; sv4.y = st[j][1]; sv4.z = st[j][2]; sv4.w = st[j][3];
            *(float4*)(attn_base + (size_t)(sA + j) * Ss + 4 * lane) = sv4;
        }

        // post-hoc (p, idx) list build into the dead scores row (warp-exclusive)
        int cnt[2];
        #pragma unroll
        for (int j = 0; j < 2; j++) {
            unsigned b0 = __ballot_sync(FULL, kx[j][0] >= thrk[j]);
            unsigned b1 = __ballot_sync(FULL, kx[j][1] >= thrk[j]);
            unsigned b2 = __ballot_sync(FULL, kx[j][2] >= thrk[j]);
            unsigned b3 = __ballot_sync(FULL, kx[j][3] >= thrk[j]);
            unsigned mbm = (1u << lane) - 1u;
            int off = __popc(b0 & mbm) + __popc(b1 & mbm) + __popc(b2 & mbm) + __popc(b3 & mbm);
            float2* row = (float2*)(sc + (sA + j) * SSTR);
            if (kx[j][0] >= thrk[j]) { row[off] = make_float2(st[j][0], __int_as_float(4*lane + 0)); off++; }
            if (kx[j][1] >= thrk[j]) { row[off] = make_float2(st[j][1], __int_as_float(4*lane + 1)); off++; }
            if (kx[j][2] >= thrk[j]) { row[off] = make_float2(st[j][2], __int_as_float(4*lane + 2)); off++; }
            if (kx[j][3] >= thrk[j]) { row[off] = make_float2(st[j][3], __int_as_float(4*lane + 3)); }
            cnt[j] = __popc(b0) + __popc(b1) + __popc(b2) + __popc(b3);
            if (cnt[j] > 64) cnt[j] = 64;   // row capacity guard (pathological tie case)
        }
        __syncwarp();

        // sparse AV from smem lists (broadcast LDS.64)
        float a0[2] = {0.f, 0.f}, a1[2] = {0.f, 0.f};
        const float2* rowA = (const float2*)(sc + sA * SSTR);
        const float2* rowB = (const float2*)(sc + (sA + 1) * SSTR);
        int cmax = cnt[0] > cnt[1] ? cnt[0] : cnt[1];
        for (int i2 = 0; i2 < cmax; i2++) {
            if (i2 < cnt[0]) {
                float2 pv = rowA[i2];
                const float* vr = vsm + __float_as_int(pv.y) * XSTR;
                a0[0] += pv.x * vr[lane];
                a1[0] += pv.x * vr[lane + 32];
            }
            if (i2 < cnt[1]) {
                float2 pv = rowB[i2];
                const float* vr = vsm + __float_as_int(pv.y) * XSTR;
                a0[1] += pv.x * vr[lane];
                a1[1] += pv.x * vr[lane + 32];
            }
        }

        // residual + LN
        float rr0[2], rr1[2], sm1[2];
        #pragma unroll
        for (int j = 0; j < 2; j++) {
            rr0[j] = a0[j] + xt_tr[(sA + j) * XSTR + lane];
            rr1[j] = a1[j] + xt_tr[(sA + j) * XSTR + lane + 32];
            sm1[j] = rr0[j] + rr1[j];
        }
        #pragma unroll
        for (int off = 16; off > 0; off >>= 1) {
            sm1[0] += __shfl_xor_sync(FULL, sm1[0], off);
            sm1[1] += __shfl_xor_sync(FULL, sm1[1], off);
        }
        float d0[2], d1[2], sq[2];
        #pragma unroll
        for (int j = 0; j < 2; j++) {
            float mu = sm1[j] * (1.0f / 64.0f);
            d0[j] = rr0[j] - mu; d1[j] = rr1[j] - mu;
            sq[j] = d0[j]*d0[j] + d1[j]*d1[j];
        }
        #pragma unroll
        for (int off = 16; off > 0; off >>= 1) {
            sq[0] += __shfl_xor_sync(FULL, sq[0], off);
            sq[1] += __shfl_xor_sync(FULL, sq[1], off);
        }
        #pragma unroll
        for (int j = 0; j < 2; j++) {
            float inv_sd = rsqrtf(sq[j] * (1.0f / 64.0f) + 1e-5f);
            float* ob = out_main + (((size_t)(b * Ss + sA + j)) * Nn + n) * Hh;
            ob[lane]      = d0[j] * inv_sd * sg[lane]      + sb[lane];
            ob[lane + 32] = d1[j] * inv_sd * sg[lane + 32] + sb[lane + 32];
        }
    }
}

extern "C" void kernel_launch(void* const* d_in, const int* in_sizes, int n_in,
                              void* d_out, int out_size) {
    const float* traffic = (const float*)d_in[0];
    const float* text    = (const float*)d_in[1];
    const float* Wq      = (const float*)d_in[2];
    const float* bq      = (const float*)d_in[3];
    const float* Wk      = (const float*)d_in[4];
    const float* bk      = (const float*)d_in[5];
    const float* Wv      = (const float*)d_in[6];
    const float* bv      = (const float*)d_in[7];
    const float* gamma   = (const float*)d_in[8];
    const float* beta    = (const float*)d_in[9];
    const int*   topk    = (n_in > 10) ? (const int*)d_in[10] : nullptr;

    float* out  = (float*)d_out;
    float* attn = out + (size_t)Bb * Ss * Nn * Hh;

    size_t smem = (size_t)SMEM_FLOATS * sizeof(float);
    cudaFuncSetAttribute(fused_align_k, cudaFuncAttributeMaxDynamicSharedMemorySize, (int)smem);

    precompute_k<<<16, 256>>>(Wq, bq, Wk, bk);
    precompute_pack<<<34, 256>>>(Wv);
    fused_align_k<<<Mm, NTH, smem>>>(traffic, text, Wv, bv, gamma, beta, topk, out, attn);
}